// round 1
// baseline (speedup 1.0000x reference)
#include <cuda_runtime.h>

// NonLocalBlock: B=8, H=W=64 (N=4096), C=256, Cb=128, pooled keys M=2048.
// out = x + softmax(theta @ phiP^T) @ gP @ W_out
//   theta = xf @ W_theta            [B,N,128]
//   phiP  = maxpool2(xf @ W_phi)    [B,M,128]
//   gP    = maxpool2(xf @ W_g)      [B,M,128]

#define NB 8
#define NN 4096
#define NM 2048
#define NC 256
#define ND 128

// Scratch (allocation-free rule: __device__ globals). ~80 MB total.
__device__ float g_theta[NB * NN * ND];
__device__ float g_phi  [NB * NN * ND];
__device__ float g_gg   [NB * NN * ND];
__device__ float g_phiP [NB * NM * ND];
__device__ float g_gP   [NB * NM * ND];
__device__ float g_y    [NB * NN * ND];

// ---------------------------------------------------------------------------
// Projection GEMM: [32768,256] @ [256,128] for 3 weights (blockIdx.z selects).
// Tile 64 rows x 128 cols, K-step 32. 256 threads, each 4x8 micro-tile.
// ---------------------------------------------------------------------------
__global__ __launch_bounds__(256) void proj_kernel(
    const float* __restrict__ x,
    const float* __restrict__ Wt,
    const float* __restrict__ Wp,
    const float* __restrict__ Wg)
{
    __shared__ float As[32][65];   // transposed A tile, padded (conflict-free)
    __shared__ float Ws[32][ND];

    const float* W;
    float* out;
    if (blockIdx.z == 0)      { W = Wt; out = g_theta; }
    else if (blockIdx.z == 1) { W = Wp; out = g_phi; }
    else                      { W = Wg; out = g_gg; }

    int tid  = threadIdx.x;
    int row0 = blockIdx.x * 64;
    int rg   = tid & 15;    // rows: rg + 16*i
    int cg   = tid >> 4;    // cols: cg*8 .. +7

    float acc[4][8];
#pragma unroll
    for (int i = 0; i < 4; i++)
#pragma unroll
        for (int j = 0; j < 8; j++) acc[i][j] = 0.f;

    for (int k0 = 0; k0 < NC; k0 += 32) {
        // A tile: 64 rows x 32 k  (512 float4), store transposed As[k][m]
#pragma unroll
        for (int q = 0; q < 2; q++) {
            int li = q * 256 + tid;
            int m  = li >> 3;
            int kk = (li & 7) * 4;
            float4 v = *(const float4*)(x + (row0 + m) * NC + k0 + kk);
            As[kk + 0][m] = v.x; As[kk + 1][m] = v.y;
            As[kk + 2][m] = v.z; As[kk + 3][m] = v.w;
        }
        // W tile: 32 x 128 (1024 float4 / 4 = 256 each? -> 4 float4/thread)
#pragma unroll
        for (int q = 0; q < 4; q++) {
            int li = q * 256 + tid;
            int kk = li >> 5;
            int c4 = (li & 31) * 4;
            *(float4*)&Ws[kk][c4] = *(const float4*)(W + (k0 + kk) * ND + c4);
        }
        __syncthreads();
#pragma unroll
        for (int k = 0; k < 32; k++) {
            float a[4];
#pragma unroll
            for (int i = 0; i < 4; i++) a[i] = As[k][rg + 16 * i];
            float4 w0 = *(float4*)&Ws[k][cg * 8];
            float4 w1 = *(float4*)&Ws[k][cg * 8 + 4];
#pragma unroll
            for (int i = 0; i < 4; i++) {
                acc[i][0] += a[i] * w0.x; acc[i][1] += a[i] * w0.y;
                acc[i][2] += a[i] * w0.z; acc[i][3] += a[i] * w0.w;
                acc[i][4] += a[i] * w1.x; acc[i][5] += a[i] * w1.y;
                acc[i][6] += a[i] * w1.z; acc[i][7] += a[i] * w1.w;
            }
        }
        __syncthreads();
    }
#pragma unroll
    for (int i = 0; i < 4; i++) {
        int r = row0 + rg + 16 * i;
        float4 v0 = make_float4(acc[i][0], acc[i][1], acc[i][2], acc[i][3]);
        float4 v1 = make_float4(acc[i][4], acc[i][5], acc[i][6], acc[i][7]);
        *(float4*)(out + r * ND + cg * 8)     = v0;
        *(float4*)(out + r * ND + cg * 8 + 4) = v1;
    }
}

// ---------------------------------------------------------------------------
// MaxPool1D(2) along spatial axis for phi and g.
// ---------------------------------------------------------------------------
__global__ __launch_bounds__(256) void pool_kernel()
{
    int idx4   = blockIdx.x * 256 + threadIdx.x;   // float4 index
    int total4 = NB * NM * ND / 4;
    if (idx4 >= total4) return;
    int d4 = idx4 % (ND / 4);
    int r  = (idx4 / (ND / 4)) % NM;
    int b  = idx4 / ((ND / 4) * NM);
    int src = ((b * NN + 2 * r) * ND) / 4 + d4;    // float4 units

    const float4* p = (const float4*)g_phi;
    const float4* g = (const float4*)g_gg;
    float4 a = p[src], a2 = p[src + ND / 4];
    float4 c = g[src], c2 = g[src + ND / 4];
    ((float4*)g_phiP)[idx4] = make_float4(fmaxf(a.x, a2.x), fmaxf(a.y, a2.y),
                                          fmaxf(a.z, a2.z), fmaxf(a.w, a2.w));
    ((float4*)g_gP)[idx4]   = make_float4(fmaxf(c.x, c2.x), fmaxf(c.y, c2.y),
                                          fmaxf(c.z, c2.z), fmaxf(c.w, c2.w));
}

// ---------------------------------------------------------------------------
// Flash-style attention: per (batch, 64-row Q tile). Online softmax over
// M=2048 keys in 64-key chunks. K and G share one smem buffer (loaded in
// two phases per chunk). Y accumulator (64x128) lives in registers.
// ---------------------------------------------------------------------------
__global__ __launch_bounds__(256, 2) void attn_kernel()
{
    extern __shared__ float sm[];
    float (*Qs)[132] = (float(*)[132])sm;                 // 64x132
    float (*KG)[132] = (float(*)[132])(sm + 64 * 132);    // 64x132 (K then G)
    float (*Ss)[65]  = (float(*)[65]) (sm + 2 * 64 * 132);// 64x65 scores/probs
    float* rowm      = sm + 2 * 64 * 132 + 64 * 65;
    float* rowl      = rowm + 64;
    float* rowscale  = rowl + 64;

    int tid = threadIdx.x;
    int b   = blockIdx.y;
    int q0  = blockIdx.x * 64;
    const float* th = g_theta + (b * NN + q0) * ND;
    const float* ph = g_phiP + b * NM * ND;
    const float* gp = g_gP   + b * NM * ND;

    // Load Q tile (64x128)
#pragma unroll
    for (int q = 0; q < 8; q++) {
        int li = q * 256 + tid;
        int r  = li >> 5;
        int c4 = (li & 31) * 4;
        *(float4*)&Qs[r][c4] = *(const float4*)(th + r * ND + c4);
    }
    if (tid < 64) { rowm[tid] = -1e30f; rowl[tid] = 0.f; }

    float yacc[32];
#pragma unroll
    for (int c = 0; c < 32; c++) yacc[c] = 0.f;
    int ry = tid & 63;           // Y row
    int c0 = (tid >> 6) * 32;    // Y col block
    int rg = tid & 15;           // score rows: rg + 16*i
    int jg = tid >> 4;           // score cols: jg + 16*j

    for (int kc = 0; kc < NM; kc += 64) {
        __syncthreads();   // protect KG/Ss from previous-iteration readers
        // Load K chunk
#pragma unroll
        for (int q = 0; q < 8; q++) {
            int li = q * 256 + tid;
            int r  = li >> 5;
            int c4 = (li & 31) * 4;
            *(float4*)&KG[r][c4] = *(const float4*)(ph + (kc + r) * ND + c4);
        }
        __syncthreads();
        // Scores: 16 (r,j) pairs/thread, k vectorized by 4
        float sacc[4][4];
#pragma unroll
        for (int i = 0; i < 4; i++)
#pragma unroll
            for (int j = 0; j < 4; j++) sacc[i][j] = 0.f;
#pragma unroll
        for (int k = 0; k < ND; k += 4) {
            float4 qv[4], kv[4];
#pragma unroll
            for (int i = 0; i < 4; i++) qv[i] = *(float4*)&Qs[rg + 16 * i][k];
#pragma unroll
            for (int j = 0; j < 4; j++) kv[j] = *(float4*)&KG[jg + 16 * j][k];
#pragma unroll
            for (int i = 0; i < 4; i++)
#pragma unroll
                for (int j = 0; j < 4; j++)
                    sacc[i][j] += qv[i].x * kv[j].x + qv[i].y * kv[j].y
                                + qv[i].z * kv[j].z + qv[i].w * kv[j].w;
        }
#pragma unroll
        for (int i = 0; i < 4; i++)
#pragma unroll
            for (int j = 0; j < 4; j++)
                Ss[rg + 16 * i][jg + 16 * j] = sacc[i][j];
        __syncthreads();
        // Reload buffer with G chunk (K reads all done)
#pragma unroll
        for (int q = 0; q < 8; q++) {
            int li = q * 256 + tid;
            int r  = li >> 5;
            int c4 = (li & 31) * 4;
            *(float4*)&KG[r][c4] = *(const float4*)(gp + (kc + r) * ND + c4);
        }
        // Online softmax (one thread per row)
        if (tid < 64) {
            int r = tid;
            float cm = -1e30f;
#pragma unroll 8
            for (int j = 0; j < 64; j++) cm = fmaxf(cm, Ss[r][j]);
            float nm = fmaxf(rowm[r], cm);
            float sc = __expf(rowm[r] - nm);
            float s  = 0.f;
#pragma unroll 8
            for (int j = 0; j < 64; j++) {
                float pv = __expf(Ss[r][j] - nm);
                Ss[r][j] = pv;
                s += pv;
            }
            rowl[r]     = rowl[r] * sc + s;
            rowm[r]     = nm;
            rowscale[r] = sc;
        }
        __syncthreads();
        // Y update: rescale + accumulate P @ G
        float sc = rowscale[ry];
#pragma unroll
        for (int c = 0; c < 32; c++) yacc[c] *= sc;
#pragma unroll 4
        for (int j = 0; j < 64; j++) {
            float pv = Ss[ry][j];
#pragma unroll
            for (int c4 = 0; c4 < 32; c4 += 4) {
                float4 gv = *(float4*)&KG[j][c0 + c4];
                yacc[c4 + 0] += pv * gv.x; yacc[c4 + 1] += pv * gv.y;
                yacc[c4 + 2] += pv * gv.z; yacc[c4 + 3] += pv * gv.w;
            }
        }
    }
    // Normalize and write y
    float inv = 1.f / rowl[ry];
    float* yo = g_y + (b * NN + q0 + ry) * ND + c0;
#pragma unroll
    for (int c4 = 0; c4 < 32; c4 += 4) {
        float4 v = make_float4(yacc[c4] * inv, yacc[c4 + 1] * inv,
                               yacc[c4 + 2] * inv, yacc[c4 + 3] * inv);
        *(float4*)(yo + c4) = v;
    }
}

// ---------------------------------------------------------------------------
// Output GEMM + residual: out = x + y @ W_out.  [32768,128] @ [128,256].
// ---------------------------------------------------------------------------
__global__ __launch_bounds__(256) void out_kernel(
    const float* __restrict__ x,
    const float* __restrict__ Wout,
    float* __restrict__ out)
{
    __shared__ float As[32][65];
    __shared__ float Ws[32][128];

    int tid  = threadIdx.x;
    int row0 = blockIdx.x * 64;
    int col0 = blockIdx.y * 128;
    int rg   = tid & 15;
    int cg   = tid >> 4;

    float acc[4][8];
#pragma unroll
    for (int i = 0; i < 4; i++)
#pragma unroll
        for (int j = 0; j < 8; j++) acc[i][j] = 0.f;

    for (int k0 = 0; k0 < ND; k0 += 32) {
#pragma unroll
        for (int q = 0; q < 2; q++) {
            int li = q * 256 + tid;
            int m  = li >> 3;
            int kk = (li & 7) * 4;
            float4 v = *(const float4*)(g_y + (row0 + m) * ND + k0 + kk);
            As[kk + 0][m] = v.x; As[kk + 1][m] = v.y;
            As[kk + 2][m] = v.z; As[kk + 3][m] = v.w;
        }
#pragma unroll
        for (int q = 0; q < 4; q++) {
            int li = q * 256 + tid;
            int kk = li >> 5;
            int c4 = (li & 31) * 4;
            *(float4*)&Ws[kk][c4] = *(const float4*)(Wout + (k0 + kk) * NC + col0 + c4);
        }
        __syncthreads();
#pragma unroll
        for (int k = 0; k < 32; k++) {
            float a[4];
#pragma unroll
            for (int i = 0; i < 4; i++) a[i] = As[k][rg + 16 * i];
            float4 w0 = *(float4*)&Ws[k][cg * 8];
            float4 w1 = *(float4*)&Ws[k][cg * 8 + 4];
#pragma unroll
            for (int i = 0; i < 4; i++) {
                acc[i][0] += a[i] * w0.x; acc[i][1] += a[i] * w0.y;
                acc[i][2] += a[i] * w0.z; acc[i][3] += a[i] * w0.w;
                acc[i][4] += a[i] * w1.x; acc[i][5] += a[i] * w1.y;
                acc[i][6] += a[i] * w1.z; acc[i][7] += a[i] * w1.w;
            }
        }
        __syncthreads();
    }
#pragma unroll
    for (int i = 0; i < 4; i++) {
        int r = row0 + rg + 16 * i;
        const float* xr = x + r * NC + col0 + cg * 8;
        float* orow     = out + r * NC + col0 + cg * 8;
        float4 x0 = *(const float4*)xr;
        float4 x1 = *(const float4*)(xr + 4);
        float4 v0 = make_float4(acc[i][0] + x0.x, acc[i][1] + x0.y,
                                acc[i][2] + x0.z, acc[i][3] + x0.w);
        float4 v1 = make_float4(acc[i][4] + x1.x, acc[i][5] + x1.y,
                                acc[i][6] + x1.z, acc[i][7] + x1.w);
        *(float4*)orow       = v0;
        *(float4*)(orow + 4) = v1;
    }
}

// ---------------------------------------------------------------------------
extern "C" void kernel_launch(void* const* d_in, const int* in_sizes, int n_in,
                              void* d_out, int out_size)
{
    const float* x  = (const float*)d_in[0];
    const float* Wt = (const float*)d_in[1];
    const float* Wp = (const float*)d_in[2];
    const float* Wg = (const float*)d_in[3];
    const float* Wo = (const float*)d_in[4];
    float* out      = (float*)d_out;

    const int ATTN_SMEM = (2 * 64 * 132 + 64 * 65 + 192) * 4;  // 84992 B
    cudaFuncSetAttribute(attn_kernel,
                         cudaFuncAttributeMaxDynamicSharedMemorySize, ATTN_SMEM);

    proj_kernel<<<dim3(512, 1, 3), 256>>>(x, Wt, Wp, Wg);
    pool_kernel<<<(NB * NM * ND / 4 + 255) / 256, 256>>>();
    attn_kernel<<<dim3(NN / 64, NB), 256, ATTN_SMEM>>>();
    out_kernel<<<dim3(512, 2), 256>>>(x, Wo, out);
}